// round 4
// baseline (speedup 1.0000x reference)
#include <cuda_runtime.h>

#define BB 10
#define CC 3
#define HH 50
#define WW 101
#define KK 4096

// Padded grid for conv1 (pad=3, row padded to 110 for float2 alignment)
#define HP 56
#define WP 110
#define SLICE (HP*WP)                 // 6160
#define GRIDP_N (BB*CC*SLICE)

// pool1 out, padded for conv2 (pad=2, rows padded to 30): [10][32][16][30]
#define P1_PAD_N (BB*32*16*30)
// pool2 out, padded for conv3 (pad=1): [10][64][8][14]
#define P2_PAD_N (BB*64*8*14)

__device__ float g_gridp[GRIDP_N];
__device__ float g_p1[P1_PAD_N];
__device__ float g_p2[P2_PAD_N];
__device__ float g_gap[BB*128];

// packed fp32x2 FMA (sm_100a): acc += a * b elementwise, exact fp32
__device__ __forceinline__ void ffma2(float2& acc, float2 a, float2 b) {
    union { float2 f; unsigned long long u; } ua, ub, uc;
    ua.f = a; ub.f = b; uc.f = acc;
    asm("fma.rn.f32x2 %0, %1, %2, %0;" : "+l"(uc.u) : "l"(ua.u), "l"(ub.u));
    acc = uc.f;
}
__device__ __forceinline__ float2 bcast2(float v) { return make_float2(v, v); }

// ---------------------------------------------------------------------------
// 1. Build grid: smem atomicMax scatter, write padded float grid [56][110].
__global__ void build_grid(const int* __restrict__ x) {
    __shared__ int s_ord[HH*WW];
    int bc = blockIdx.x;
    for (int i = threadIdx.x; i < HH*WW; i += blockDim.x) s_ord[i] = -1;
    __syncthreads();
    const int2* xp = (const int2*)x;
    for (int k = threadIdx.x; k < KK + 1; k += blockDim.x) {
        int col, row;
        if (k == 0) { col = 50; row = 48; }
        else { int2 p = xp[bc*KK + k - 1]; col = p.x; row = p.y; }
        int base = row * WW + col;
        int o = k * 10;
        atomicMax(&s_ord[base-WW-1], o+0);
        atomicMax(&s_ord[base-WW  ], o+1);
        atomicMax(&s_ord[base-WW+1], o+2);
        atomicMax(&s_ord[base-1   ], o+3);
        atomicMax(&s_ord[base+1   ], o+5);
        atomicMax(&s_ord[base+WW-1], o+6);
        atomicMax(&s_ord[base+WW  ], o+7);
        atomicMax(&s_ord[base+WW+1], o+8);
        atomicMax(&s_ord[base     ], o+9);
    }
    __syncthreads();
    float* gp = g_gridp + bc * SLICE;
    for (int q = threadIdx.x; q < SLICE; q += blockDim.x) {
        int r = q / WP, cl = q % WP;
        float v = 0.f;
        if (r >= 3 && r < 3+HH && cl >= 3 && cl < 3+WW) {
            int o = s_ord[(r-3)*WW + (cl-3)];
            if (o >= 0) v = ((o % 10) == 9) ? 1.0f : 0.5f;
        }
        gp[q] = v;
    }
}

// ---------------------------------------------------------------------------
// 2. conv1 7x7 s2 (3->32) + relu + pool 3x3 s2 -> padded [16][30].
//    Block=(b, co-pair): 160 x 100. Thread: 2co x 13ow (row tile, 13 chains).
__global__ void conv1_pool1(const float* __restrict__ w1, const float* __restrict__ b1) {
    extern __shared__ float sm[];
    float* s_in = sm;              // 3*6160 = 18480
    float* s_w  = sm + 18480;      // 147*2 = 294 (+pad)
    float* s_c  = sm + 18776;      // 2*25*51 = 2550
    int b = blockIdx.x >> 4, cp = blockIdx.x & 15;
    int co0 = cp * 2;
    {
        const float4* src = (const float4*)(g_gridp + b * 3 * SLICE);
        float4* dst = (float4*)s_in;
        for (int i = threadIdx.x; i < 3*SLICE/4; i += 100) dst[i] = src[i];
        for (int i = threadIdx.x; i < 294; i += 100)
            s_w[i] = w1[(co0 + (i & 1)) * 147 + (i >> 1)];
    }
    __syncthreads();
    {
        int oh = threadIdx.x / 4, owt = threadIdx.x & 3;
        int ow0 = owt * 13;
        int count = (owt < 3) ? 13 : 12;
        float2 bias = make_float2(b1[co0], b1[co0+1]);
        float2 acc[13];
#pragma unroll
        for (int t = 0; t < 13; t++) acc[t] = bias;
        const float2* wv = (const float2*)s_w;
#pragma unroll
        for (int ci = 0; ci < 3; ci++) {
#pragma unroll
            for (int kh = 0; kh < 7; kh++) {
                const float2* rp = (const float2*)(s_in + ci*SLICE + (oh*2 + kh)*WP + ow0*2);
                float fl[32];
#pragma unroll
                for (int m = 0; m < 16; m++) { float2 p = rp[m]; fl[2*m] = p.x; fl[2*m+1] = p.y; }
#pragma unroll
                for (int kw = 0; kw < 7; kw++) {
                    float2 w = wv[ci*49 + kh*7 + kw];
#pragma unroll
                    for (int t = 0; t < 13; t++)
                        ffma2(acc[t], bcast2(fl[2*t + kw]), w);
                }
            }
        }
        for (int t = 0; t < count; t++) {
            s_c[oh*51 + ow0 + t]        = fmaxf(acc[t].x, 0.f);
            s_c[1275 + oh*51 + ow0 + t] = fmaxf(acc[t].y, 0.f);
        }
    }
    __syncthreads();
    for (int q = threadIdx.x; q < 2*16*30; q += 100) {
        int u = q / 480, rc = q % 480, r = rc / 30, cl = rc % 30;
        float v = 0.f;
        if (r >= 2 && r < 14 && cl >= 2 && cl < 27) {
            const float* c = s_c + u*1275 + ((r-2)*2)*51 + (cl-2)*2;
            float m = fmaxf(fmaxf(c[0], c[1]), c[2]);
            m = fmaxf(m, fmaxf(fmaxf(c[51], c[52]), c[53]));
            v = fmaxf(m, fmaxf(fmaxf(c[102], c[103]), c[104]));
        }
        g_p1[((b*32 + co0 + u) * 16 + r) * 30 + cl] = v;
    }
}

// ---------------------------------------------------------------------------
// 3. conv2 5x5 (32->64) + relu + pool 2x2 -> padded [8][14].
//    Block=(b, 4co): 160 x 192. ciq=4 x pair=2 x oh=12 x half=2.
//    Thread: 2co x 12/13 ow half-row over 8 ci.
__global__ void conv2_pool2(const float* __restrict__ w2, const float* __restrict__ b2) {
    extern __shared__ float sm[];
    float* s_in   = sm;            // 32*16*30 = 15360
    float* s_w    = sm + 15360;    // 32*25*2pair*2 = 3200
    float* s_part = sm + 18560;    // 192*26 = 4992
    float* s_c    = sm + 23552;    // 4*300 = 1200
    int b = blockIdx.x >> 4, cog = blockIdx.x & 15;
    {
        const float4* src = (const float4*)(g_p1 + b * 15360);
        float4* dst = (float4*)s_in;
        for (int i = threadIdx.x; i < 3840; i += 192) dst[i] = src[i];
        for (int i = threadIdx.x; i < 3200; i += 192) {
            int coin = i & 1, pr = (i >> 1) & 1, j = i >> 2;
            s_w[i] = w2[(cog*4 + pr*2 + coin) * 800 + j];
        }
    }
    __syncthreads();
    {
        int ciq = threadIdx.x / 48;
        int rem = threadIdx.x % 48;
        int pair = rem / 24;
        int oh = (rem % 24) / 2, half = rem & 1;
        int ow0 = half * 12;
        int count = half ? 13 : 12;
        float2 acc[13] = {};
        const float2* wv = (const float2*)s_w;   // [(ci*25+k)*2 + pair]
        int ci0 = ciq * 8;
        for (int ci = ci0; ci < ci0 + 8; ci++) {
#pragma unroll
            for (int kh = 0; kh < 5; kh++) {
                const float2* rp = (const float2*)(s_in + ci*480 + (oh+kh)*30 + ow0);
                float fl[18];
#pragma unroll
                for (int m = 0; m < 9; m++) { float2 p = rp[m]; fl[2*m] = p.x; fl[2*m+1] = p.y; }
#pragma unroll
                for (int kw = 0; kw < 5; kw++) {
                    float2 w = wv[(ci*25 + kh*5 + kw)*2 + pair];
#pragma unroll
                    for (int t = 0; t < 13; t++)
                        ffma2(acc[t], bcast2(fl[t + kw]), w);
                }
            }
        }
        float* pp = s_part + threadIdx.x * 26;
        for (int t = 0; t < count; t++) { pp[t*2] = acc[t].x; pp[t*2+1] = acc[t].y; }
    }
    __syncthreads();
    for (int o = threadIdx.x; o < 1200; o += 192) {
        int co_l = o / 300, rem = o % 300;
        int oh = rem / 25, ow = rem % 25;
        int pair = co_l >> 1, coin = co_l & 1;
        int half = (ow >= 12) ? 1 : 0;
        int t = ow - half * 12;
        int sub = pair*24 + oh*2 + half;
        float v = s_part[(sub      )*26 + t*2 + coin]
                + s_part[(48  + sub)*26 + t*2 + coin]
                + s_part[(96  + sub)*26 + t*2 + coin]
                + s_part[(144 + sub)*26 + t*2 + coin]
                + b2[cog*4 + co_l];
        s_c[co_l*300 + oh*25 + ow] = fmaxf(v, 0.f);
    }
    __syncthreads();
    for (int q = threadIdx.x; q < 4*8*14; q += 192) {
        int u = q / 112, rc = q % 112, rr = rc / 14, cl = rc % 14;
        float v = 0.f;
        if (rr >= 1 && rr < 7 && cl >= 1 && cl < 13) {
            const float* c = s_c + u*300 + ((rr-1)*2)*25 + (cl-1)*2;
            v = fmaxf(fmaxf(c[0], c[1]), fmaxf(c[25], c[26]));
        }
        g_p2[((b*64 + cog*4 + u) * 8 + rr) * 14 + cl] = v;
    }
}

// ---------------------------------------------------------------------------
// 4. conv3 3x3 (64->128) + relu + pool 2x2 + global-avg.
//    Block=(b, 8co): 160 x 96. ciq=4 x pair=4 x oh=6. Thread: 2co x 12ow row.
__global__ void conv3_gap(const float* __restrict__ w3, const float* __restrict__ b3) {
    extern __shared__ float sm[];
    float* s_in   = sm;            // 64*8*14 = 7168
    float* s_w    = sm + 7168;     // 64*9*4pair*2 = 4608
    float* s_part = sm + 11776;    // 96*24 = 2304
    float* s_c    = sm + 14080;    // 8*72 = 576
    float* s_p    = sm + 14656;    // 8*18 = 144
    int b = blockIdx.x >> 4, cog = blockIdx.x & 15;
    {
        const float4* src = (const float4*)(g_p2 + b * 7168);
        float4* dst = (float4*)s_in;
        for (int i = threadIdx.x; i < 1792; i += 96) dst[i] = src[i];
        for (int i = threadIdx.x; i < 4608; i += 96) {
            int coin = i & 1, pr = (i >> 1) & 3, j = i >> 3;
            s_w[i] = w3[(cog*8 + pr*2 + coin) * 576 + j];
        }
    }
    __syncthreads();
    {
        int ciq = threadIdx.x / 24;
        int rem = threadIdx.x % 24;
        int pair = rem / 6, oh = rem % 6;
        float2 acc[12] = {};
        const float2* wv = (const float2*)s_w;   // [(ci*9+k)*4 + pair]
        int ci0 = ciq * 16;
        for (int ci = ci0; ci < ci0 + 16; ci++) {
#pragma unroll
            for (int kh = 0; kh < 3; kh++) {
                const float2* rp = (const float2*)(s_in + ci*112 + (oh+kh)*14);
                float fl[14];
#pragma unroll
                for (int m = 0; m < 7; m++) { float2 p = rp[m]; fl[2*m] = p.x; fl[2*m+1] = p.y; }
#pragma unroll
                for (int kw = 0; kw < 3; kw++) {
                    float2 w = wv[(ci*9 + kh*3 + kw)*4 + pair];
#pragma unroll
                    for (int t = 0; t < 12; t++)
                        ffma2(acc[t], bcast2(fl[t + kw]), w);
                }
            }
        }
        float* pp = s_part + threadIdx.x * 24;
#pragma unroll
        for (int t = 0; t < 12; t++) { pp[t*2] = acc[t].x; pp[t*2+1] = acc[t].y; }
    }
    __syncthreads();
#pragma unroll
    for (int i = 0; i < 6; i++) {
        int o = threadIdx.x + i * 96;           // 576 outputs
        int co_l = o / 72, rem = o % 72;
        int oh = rem / 12, ow = rem % 12;
        int pair = co_l >> 1, coin = co_l & 1;
        int sub = pair*6 + oh;
        float v = s_part[(sub     )*24 + ow*2 + coin]
                + s_part[(24 + sub)*24 + ow*2 + coin]
                + s_part[(48 + sub)*24 + ow*2 + coin]
                + s_part[(72 + sub)*24 + ow*2 + coin]
                + b3[cog*8 + co_l];
        s_c[co_l*72 + oh*12 + ow] = fmaxf(v, 0.f);
    }
    __syncthreads();
    for (int q = threadIdx.x; q < 144; q += 96) {
        int co_l = q / 18, cell = q % 18;
        int ph = cell / 6, pw = cell % 6;
        const float* c = s_c + co_l*72 + (ph*2)*12 + pw*2;
        s_p[q] = fmaxf(fmaxf(c[0], c[1]), fmaxf(c[12], c[13]));
    }
    __syncthreads();
    if (threadIdx.x < 8) {
        float s = 0.f;
#pragma unroll
        for (int i = 0; i < 18; i++) s += s_p[threadIdx.x*18 + i];
        g_gap[b*128 + cog*8 + threadIdx.x] = s * (1.0f/18.0f);
    }
}

// ---------------------------------------------------------------------------
// 5. fc1(128->128)+relu, fc2(128->5). One block per batch row.
__global__ void fc_fused(const float* __restrict__ wl1, const float* __restrict__ bl1,
                         const float* __restrict__ wl2, const float* __restrict__ bl2,
                         float* __restrict__ out) {
    __shared__ float s_g[128];
    __shared__ float s_h[128];
    int b = blockIdx.x;
    int t = threadIdx.x;
    s_g[t] = g_gap[b*128 + t];
    __syncthreads();
    float s = bl1[t];
    const float* wr = wl1 + t*128;
#pragma unroll 8
    for (int i = 0; i < 128; i++) s += s_g[i] * wr[i];
    s_h[t] = fmaxf(s, 0.f);
    __syncthreads();
    if (t < 5) {
        float o = bl2[t];
        const float* wr2 = wl2 + t*128;
#pragma unroll 8
        for (int i = 0; i < 128; i++) o += s_h[i] * wr2[i];
        out[b*5 + t] = o;
    }
}

extern "C" void kernel_launch(void* const* d_in, const int* in_sizes, int n_in,
                              void* d_out, int out_size) {
    const int*   x   = (const int*)  d_in[0];
    const float* w1  = (const float*)d_in[1];
    const float* b1  = (const float*)d_in[2];
    const float* w2  = (const float*)d_in[3];
    const float* b2  = (const float*)d_in[4];
    const float* w3  = (const float*)d_in[5];
    const float* b3  = (const float*)d_in[6];
    const float* wl1 = (const float*)d_in[7];
    const float* bl1 = (const float*)d_in[8];
    const float* wl2 = (const float*)d_in[9];
    const float* bl2 = (const float*)d_in[10];
    float* out = (float*)d_out;

    const int smem1 = (18480 + 296 + 2550) * 4;             // 85304 B
    const int smem2 = (15360 + 3200 + 4992 + 1200) * 4;     // 99008 B
    const int smem3 = (7168 + 4608 + 2304 + 576 + 144) * 4; // 59200 B
    cudaFuncSetAttribute(conv1_pool1, cudaFuncAttributeMaxDynamicSharedMemorySize, smem1);
    cudaFuncSetAttribute(conv2_pool2, cudaFuncAttributeMaxDynamicSharedMemorySize, smem2);
    cudaFuncSetAttribute(conv3_gap,   cudaFuncAttributeMaxDynamicSharedMemorySize, smem3);

    build_grid <<<BB*CC, 1024>>>(x);
    conv1_pool1<<<BB*16, 100, smem1>>>(w1, b1);
    conv2_pool2<<<BB*16, 192, smem2>>>(w2, b2);
    conv3_gap  <<<BB*16, 96,  smem3>>>(w3, b3);
    fc_fused   <<<BB, 128>>>(wl1, bl1, wl2, bl2, out);
}

// round 5
// speedup vs baseline: 1.0698x; 1.0698x over previous
#include <cuda_runtime.h>

#define BB 10
#define CC 3
#define HH 50
#define WW 101
#define KK 4096

// Padded grid for conv1 (pad=3, rows padded to 110): [30][56][110]
#define HP 56
#define WP 110
#define SLICE (HP*WP)                 // 6160
#define GRIDP_N (BB*CC*SLICE)

// pool1 out, padded for conv2 (pad=2, rows 30): [10][32][16][30]
#define P1_PAD_N (BB*32*16*30)
// pool2 out, padded for conv3 (pad=1): [10][64][8][14]
#define P2_PAD_N (BB*64*8*14)

__device__ float g_gridp[GRIDP_N];
__device__ float g_p1[P1_PAD_N];   // zero-initialized; borders never written
__device__ float g_p2[P2_PAD_N];   // zero-initialized; borders never written
__device__ float g_gap[BB*128];

// packed fp32x2 FMA (sm_100a): acc += a * b elementwise, exact fp32
__device__ __forceinline__ void ffma2(float2& acc, float2 a, float2 b) {
    union { float2 f; unsigned long long u; } ua, ub, uc;
    ua.f = a; ub.f = b; uc.f = acc;
    asm("fma.rn.f32x2 %0, %1, %2, %0;" : "+l"(uc.u) : "l"(ua.u), "l"(ub.u));
    acc = uc.f;
}
__device__ __forceinline__ float2 bcast2(float v) { return make_float2(v, v); }

// ---------------------------------------------------------------------------
// 1. Build grid: smem atomicMax scatter, write padded float grid [56][110].
__global__ void build_grid(const int* __restrict__ x) {
    __shared__ int s_ord[HH*WW];
    int bc = blockIdx.x;
    for (int i = threadIdx.x; i < HH*WW; i += blockDim.x) s_ord[i] = -1;
    __syncthreads();
    const int2* xp = (const int2*)x;
    for (int k = threadIdx.x; k < KK + 1; k += blockDim.x) {
        int col, row;
        if (k == 0) { col = 50; row = 48; }
        else { int2 p = xp[bc*KK + k - 1]; col = p.x; row = p.y; }
        int base = row * WW + col;
        int o = k * 10;
        atomicMax(&s_ord[base-WW-1], o+0);
        atomicMax(&s_ord[base-WW  ], o+1);
        atomicMax(&s_ord[base-WW+1], o+2);
        atomicMax(&s_ord[base-1   ], o+3);
        atomicMax(&s_ord[base+1   ], o+5);
        atomicMax(&s_ord[base+WW-1], o+6);
        atomicMax(&s_ord[base+WW  ], o+7);
        atomicMax(&s_ord[base+WW+1], o+8);
        atomicMax(&s_ord[base     ], o+9);
    }
    __syncthreads();
    float* gp = g_gridp + bc * SLICE;
    for (int q = threadIdx.x; q < SLICE; q += blockDim.x) {
        int r = q / WP, cl = q % WP;
        float v = 0.f;
        if (r >= 3 && r < 3+HH && cl >= 3 && cl < 3+WW) {
            int o = s_ord[(r-3)*WW + (cl-3)];
            if (o >= 0) v = ((o % 10) == 9) ? 1.0f : 0.5f;
        }
        gp[q] = v;
    }
}

// ---------------------------------------------------------------------------
// 2. conv1 7x7 s2 (3->32) + relu + pool 3x3 s2 (3 pool rows per block).
//    Grid = (b10 x cp16 x g4) = 640 blocks x 384 threads.
//    Thread: one (oh,ow) conv output x 2 co (f32x2). 7 conv rows incl. halo.
__global__ void __launch_bounds__(384) conv1_pool1(const float* __restrict__ w1,
                                                   const float* __restrict__ b1) {
    extern __shared__ float sm[];
    float* s_in = sm;              // 3*19*110 = 6270
    float* s_w  = sm + 6270;       // 294
    float* s_c  = sm + 6566;       // 2*7*51 = 714
    int bx = blockIdx.x;
    int b = bx >> 6, r = bx & 63;
    int cp = r >> 2, g = r & 3;
    int co0 = cp * 2;
    int row0 = 12 * g;             // padded input row base
    {
        const float2* src = (const float2*)(g_gridp + b * 3 * SLICE);
        float2* dst = (float2*)s_in;
        for (int i = threadIdx.x; i < 3*19*55; i += 384) {
            int ci = i / (19*55), rr = (i % (19*55)) / 55, cc = i % 55;
            dst[i] = src[ci*(SLICE/2) + (row0+rr)*55 + cc];
        }
        for (int i = threadIdx.x; i < 294; i += 384)
            s_w[i] = w1[(co0 + (i & 1)) * 147 + (i >> 1)];
    }
    __syncthreads();
    if (threadIdx.x < 357) {
        int oh_l = threadIdx.x / 51, ow = threadIdx.x % 51;
        float2 acc = make_float2(b1[co0], b1[co0+1]);
        const float2* wv = (const float2*)s_w;
#pragma unroll
        for (int ci = 0; ci < 3; ci++) {
#pragma unroll
            for (int kh = 0; kh < 7; kh++) {
                const float2* rp = (const float2*)(s_in + ci*2090 + (oh_l*2 + kh)*110 + ow*2);
                float2 p0 = rp[0], p1 = rp[1], p2 = rp[2], p3 = rp[3];
                float v[7] = {p0.x, p0.y, p1.x, p1.y, p2.x, p2.y, p3.x};
#pragma unroll
                for (int kw = 0; kw < 7; kw++)
                    ffma2(acc, bcast2(v[kw]), wv[ci*49 + kh*7 + kw]);
            }
        }
        s_c[oh_l*51 + ow]       = fmaxf(acc.x, 0.f);
        s_c[357 + oh_l*51 + ow] = fmaxf(acc.y, 0.f);
    }
    __syncthreads();
    // pool 3x3 s2: 3 pool rows x 25 cols x 2 co -> padded interior of g_p1
    if (threadIdx.x < 150) {
        int u = threadIdx.x / 75, q = threadIdx.x % 75;
        int pr = q / 25, pc = q % 25;
        const float* c = s_c + u*357 + (pr*2)*51 + pc*2;
        float m = fmaxf(fmaxf(c[0], c[1]), c[2]);
        m = fmaxf(m, fmaxf(fmaxf(c[51], c[52]), c[53]));
        m = fmaxf(m, fmaxf(fmaxf(c[102], c[103]), c[104]));
        g_p1[((b*32 + co0 + u) * 16 + (2 + 3*g + pr)) * 30 + (2 + pc)] = m;
    }
}

// ---------------------------------------------------------------------------
// 3. conv2 5x5 (32->64) + relu + pool 2x2 -> g_p2 interior.
//    Grid = (b10 x cog32 of 2co) = 320 blocks x 480 threads.
//    Thread: ciq(8 of 4ci) x oh(12) x owt(5 of 5ow); 5 float2 chains.
__global__ void __launch_bounds__(480) conv2_pool2(const float* __restrict__ w2,
                                                   const float* __restrict__ b2) {
    extern __shared__ float sm[];
    float* s_in   = sm;            // 32*16*30 = 15360
    float* s_w    = sm + 15360;    // 2*800 = 1600 (co-interleaved)
    float* s_part = sm + 16960;    // 8*600 = 4800
    float* s_c    = sm + 21760;    // 2*300 = 600
    int b = blockIdx.x >> 5, cog = blockIdx.x & 31;
    int co0 = cog * 2;
    {
        const float4* src = (const float4*)(g_p1 + b * 15360);
        float4* dst = (float4*)s_in;
        for (int i = threadIdx.x; i < 3840; i += 480) dst[i] = src[i];
        for (int i = threadIdx.x; i < 1600; i += 480)
            s_w[i] = w2[(co0 + (i & 1)) * 800 + (i >> 1)];
    }
    __syncthreads();
    {
        int ciq = threadIdx.x / 60, rem = threadIdx.x % 60;
        int oh = rem / 5, ow0 = (rem % 5) * 5;
        float2 acc[5] = {};
        const float2* wv = (const float2*)s_w;
        int ci0 = ciq * 4;
#pragma unroll
        for (int ci = ci0; ci < ci0 + 4; ci++) {
#pragma unroll
            for (int kh = 0; kh < 5; kh++) {
                const float* rp = s_in + ci*480 + (oh + kh)*30 + ow0;
                float v[9];
#pragma unroll
                for (int m = 0; m < 9; m++) v[m] = rp[m];
#pragma unroll
                for (int kw = 0; kw < 5; kw++) {
                    float2 w = wv[ci*25 + kh*5 + kw];
#pragma unroll
                    for (int t = 0; t < 5; t++)
                        ffma2(acc[t], bcast2(v[kw+t]), w);
                }
            }
        }
        float* pp = s_part + ciq*600 + oh*50 + ow0*2;
#pragma unroll
        for (int t = 0; t < 5; t++) { pp[t*2] = acc[t].x; pp[t*2+1] = acc[t].y; }
    }
    __syncthreads();
    for (int o = threadIdx.x; o < 600; o += 480) {
        int coin = o & 1, pos = o >> 1;       // pos = oh*25 + ow
        float v = b2[co0 + coin];
#pragma unroll
        for (int q = 0; q < 8; q++) v += s_part[q*600 + o];
        s_c[coin*300 + pos] = fmaxf(v, 0.f);
    }
    __syncthreads();
    if (threadIdx.x < 144) {
        int u = threadIdx.x / 72, rc = threadIdx.x % 72;
        int rr = rc / 12, cl = rc % 12;
        const float* c = s_c + u*300 + (rr*2)*25 + cl*2;
        float v = fmaxf(fmaxf(c[0], c[1]), fmaxf(c[25], c[26]));
        g_p2[((b*64 + co0 + u) * 8 + (rr + 1)) * 14 + (cl + 1)] = v;
    }
}

// ---------------------------------------------------------------------------
// 4. conv3 3x3 (64->128) + relu + pool 2x2 + global-avg.
//    Grid = (b10 x cog32 of 4co) = 320 blocks x 288 threads.
//    Thread: ciq(8 of 8ci) x pair(2) x oh(6) x owq(3 of 4ow); 4 float2 chains.
__global__ void __launch_bounds__(288) conv3_gap(const float* __restrict__ w3,
                                                 const float* __restrict__ b3) {
    extern __shared__ float sm[];
    float* s_in   = sm;            // 64*8*14 = 7168
    float* s_w    = sm + 7168;     // 4*576 = 2304 (pair/coin interleaved)
    float* s_part = sm + 9472;     // 8*288 = 2304
    float* s_c    = sm + 11776;    // 4*72 = 288
    float* s_p    = sm + 12064;    // 72
    int b = blockIdx.x >> 5, cog = blockIdx.x & 31;
    int cb = cog * 4;
    {
        const float4* src = (const float4*)(g_p2 + b * 7168);
        float4* dst = (float4*)s_in;
        for (int i = threadIdx.x; i < 1792; i += 288) dst[i] = src[i];
        for (int i = threadIdx.x; i < 2304; i += 288) {
            int coin = i & 1, pr = (i >> 1) & 1, j = i >> 2;
            s_w[i] = w3[(cb + pr*2 + coin) * 576 + j];
        }
    }
    __syncthreads();
    {
        int ciq = threadIdx.x / 36, sub = threadIdx.x % 36;
        int pair = sub / 18, oh = (sub % 18) / 3, owq = sub % 3;
        int ow0 = owq * 4;
        float2 acc[4] = {};
        const float2* wv = (const float2*)s_w;
        int ci0 = ciq * 8;
#pragma unroll
        for (int ci = ci0; ci < ci0 + 8; ci++) {
#pragma unroll
            for (int kh = 0; kh < 3; kh++) {
                const float2* rp = (const float2*)(s_in + ci*112 + (oh + kh)*14 + ow0);
                float2 p0 = rp[0], p1 = rp[1], p2 = rp[2];
                float v[6] = {p0.x, p0.y, p1.x, p1.y, p2.x, p2.y};
#pragma unroll
                for (int kw = 0; kw < 3; kw++) {
                    float2 w = wv[(ci*9 + kh*3 + kw)*2 + pair];
#pragma unroll
                    for (int t = 0; t < 4; t++)
                        ffma2(acc[t], bcast2(v[kw+t]), w);
                }
            }
        }
        float* pp = s_part + ciq*288 + sub*8;
#pragma unroll
        for (int t = 0; t < 4; t++) { pp[t*2] = acc[t].x; pp[t*2+1] = acc[t].y; }
    }
    __syncthreads();
    {
        int t = threadIdx.x;                  // 288 outputs
        int j = t & 7, s2 = t >> 3;
        int ti = j >> 1, coin = j & 1;
        int pr = s2 / 18, oh2 = (s2 % 18) / 3, oq = s2 % 3;
        int co_l = pr*2 + coin, ow = oq*4 + ti;
        float v = b3[cb + co_l];
#pragma unroll
        for (int q = 0; q < 8; q++) v += s_part[q*288 + t];
        s_c[co_l*72 + oh2*12 + ow] = fmaxf(v, 0.f);
    }
    __syncthreads();
    if (threadIdx.x < 72) {
        int co_l = threadIdx.x / 18, cell = threadIdx.x % 18;
        int ph = cell / 6, pw = cell % 6;
        const float* c = s_c + co_l*72 + (ph*2)*12 + pw*2;
        s_p[threadIdx.x] = fmaxf(fmaxf(c[0], c[1]), fmaxf(c[12], c[13]));
    }
    __syncthreads();
    if (threadIdx.x < 4) {
        float s = 0.f;
#pragma unroll
        for (int i = 0; i < 18; i++) s += s_p[threadIdx.x*18 + i];
        g_gap[b*128 + cb + threadIdx.x] = s * (1.0f/18.0f);
    }
}

// ---------------------------------------------------------------------------
// 5. fc1(128->128)+relu, fc2(128->5). One block per batch row.
__global__ void fc_fused(const float* __restrict__ wl1, const float* __restrict__ bl1,
                         const float* __restrict__ wl2, const float* __restrict__ bl2,
                         float* __restrict__ out) {
    __shared__ float s_g[128];
    __shared__ float s_h[128];
    int b = blockIdx.x;
    int t = threadIdx.x;
    s_g[t] = g_gap[b*128 + t];
    __syncthreads();
    float s = bl1[t];
    const float* wr = wl1 + t*128;
#pragma unroll 8
    for (int i = 0; i < 128; i++) s += s_g[i] * wr[i];
    s_h[t] = fmaxf(s, 0.f);
    __syncthreads();
    if (t < 5) {
        float o = bl2[t];
        const float* wr2 = wl2 + t*128;
#pragma unroll 8
        for (int i = 0; i < 128; i++) o += s_h[i] * wr2[i];
        out[b*5 + t] = o;
    }
}

extern "C" void kernel_launch(void* const* d_in, const int* in_sizes, int n_in,
                              void* d_out, int out_size) {
    const int*   x   = (const int*)  d_in[0];
    const float* w1  = (const float*)d_in[1];
    const float* b1  = (const float*)d_in[2];
    const float* w2  = (const float*)d_in[3];
    const float* b2  = (const float*)d_in[4];
    const float* w3  = (const float*)d_in[5];
    const float* b3  = (const float*)d_in[6];
    const float* wl1 = (const float*)d_in[7];
    const float* bl1 = (const float*)d_in[8];
    const float* wl2 = (const float*)d_in[9];
    const float* bl2 = (const float*)d_in[10];
    float* out = (float*)d_out;

    const int smem1 = (6270 + 294 + 2 + 714) * 4;           // 29120 B
    const int smem2 = (15360 + 1600 + 4800 + 600) * 4;      // 89440 B
    const int smem3 = (7168 + 2304 + 2304 + 288 + 72) * 4;  // 48544 B
    cudaFuncSetAttribute(conv1_pool1, cudaFuncAttributeMaxDynamicSharedMemorySize, smem1);
    cudaFuncSetAttribute(conv2_pool2, cudaFuncAttributeMaxDynamicSharedMemorySize, smem2);
    cudaFuncSetAttribute(conv3_gap,   cudaFuncAttributeMaxDynamicSharedMemorySize, smem3);

    build_grid <<<BB*CC, 1024>>>(x);
    conv1_pool1<<<BB*64, 384, smem1>>>(w1, b1);
    conv2_pool2<<<BB*32, 480, smem2>>>(w2, b2);
    conv3_gap  <<<BB*32, 288, smem3>>>(w3, b3);
    fc_fused   <<<BB, 128>>>(wl1, bl1, wl2, bl2, out);
}

// round 6
// speedup vs baseline: 1.1616x; 1.0858x over previous
#include <cuda_runtime.h>

#define BB 10
#define CC 3
#define HH 50
#define WW 101
#define KK 4096

// Padded grid for conv1 (pad=3, rows padded to 110): [30][56][110]
#define HP 56
#define WP 110
#define SLICE (HP*WP)                 // 6160
#define GRIDP_N (BB*CC*SLICE)

// pool1 out, padded for conv2 (pad=2, rows 30): [10][32][16][30]
#define P1_PAD_N (BB*32*16*30)
// pool2 out, padded for conv3 (pad=1): [10][64][8][14]
#define P2_PAD_N (BB*64*8*14)

__device__ float g_gridp[GRIDP_N];
__device__ float g_p1[P1_PAD_N];   // zero-initialized; borders never written
__device__ float g_p2[P2_PAD_N];   // zero-initialized; borders never written
__device__ float g_gap[BB*128];

// packed fp32x2 FMA (sm_100a): acc += a * b elementwise, exact fp32
__device__ __forceinline__ void ffma2(float2& acc, float2 a, float2 b) {
    union { float2 f; unsigned long long u; } ua, ub, uc;
    ua.f = a; ub.f = b; uc.f = acc;
    asm("fma.rn.f32x2 %0, %1, %2, %0;" : "+l"(uc.u) : "l"(ua.u), "l"(ub.u));
    acc = uc.f;
}
__device__ __forceinline__ float2 bcast2(float v) { return make_float2(v, v); }

// ---------------------------------------------------------------------------
// 1. Build grid: smem atomicMax scatter, write padded float grid [56][110].
__global__ void build_grid(const int* __restrict__ x) {
    __shared__ int s_ord[HH*WW];
    int bc = blockIdx.x;
    for (int i = threadIdx.x; i < HH*WW; i += blockDim.x) s_ord[i] = -1;
    __syncthreads();
    const int2* xp = (const int2*)x;
    for (int k = threadIdx.x; k < KK + 1; k += blockDim.x) {
        int col, row;
        if (k == 0) { col = 50; row = 48; }
        else { int2 p = xp[bc*KK + k - 1]; col = p.x; row = p.y; }
        int base = row * WW + col;
        int o = k * 10;
        atomicMax(&s_ord[base-WW-1], o+0);
        atomicMax(&s_ord[base-WW  ], o+1);
        atomicMax(&s_ord[base-WW+1], o+2);
        atomicMax(&s_ord[base-1   ], o+3);
        atomicMax(&s_ord[base+1   ], o+5);
        atomicMax(&s_ord[base+WW-1], o+6);
        atomicMax(&s_ord[base+WW  ], o+7);
        atomicMax(&s_ord[base+WW+1], o+8);
        atomicMax(&s_ord[base     ], o+9);
    }
    __syncthreads();
    float* gp = g_gridp + bc * SLICE;
    for (int q = threadIdx.x; q < SLICE; q += blockDim.x) {
        int r = q / WP, cl = q % WP;
        float v = 0.f;
        if (r >= 3 && r < 3+HH && cl >= 3 && cl < 3+WW) {
            int o = s_ord[(r-3)*WW + (cl-3)];
            if (o >= 0) v = ((o % 10) == 9) ? 1.0f : 0.5f;
        }
        gp[q] = v;
    }
}

// ---------------------------------------------------------------------------
// 2. conv1 7x7 s2 (3->32) + relu + pool 3x3 s2 (3 pool rows per block).
//    Grid = (b10 x cq8 of 4co x g4) = 320 blocks x 128 threads.
//    Thread: 3 ow x 4 co (2 f32x2 pairs), ~6 resident blocks/SM.
__global__ void __launch_bounds__(128) conv1_pool1(const float* __restrict__ w1,
                                                   const float* __restrict__ b1) {
    extern __shared__ float sm[];
    float* s_in = sm;              // 3*19*110 = 6270
    float* s_w  = sm + 6270;       // 147*4 = 588  [j][pr][coin]
    float* s_c  = sm + 6860;       // 4*357 = 1428
    int bx = blockIdx.x;
    int b = bx >> 5, r = bx & 31;
    int cq = r >> 2, g = r & 3;
    int co0 = cq * 4;
    int row0 = 12 * g;
    {
        const float2* src = (const float2*)(g_gridp + b * 3 * SLICE);
        float2* dst = (float2*)s_in;
        for (int i = threadIdx.x; i < 3*19*55; i += 128) {
            int ci = i / (19*55), rr = (i % (19*55)) / 55, cc = i % 55;
            dst[i] = src[ci*(SLICE/2) + (row0+rr)*55 + cc];
        }
        for (int i = threadIdx.x; i < 588; i += 128) {
            int coin = i & 1, pr = (i >> 1) & 1, j = i >> 2;
            s_w[i] = w1[(co0 + pr*2 + coin) * 147 + j];
        }
    }
    __syncthreads();
    if (threadIdx.x < 119) {
        int oh = threadIdx.x / 17, owt = threadIdx.x % 17;
        int ow0 = owt * 3;
        float2 bias0 = make_float2(b1[co0],   b1[co0+1]);
        float2 bias1 = make_float2(b1[co0+2], b1[co0+3]);
        float2 acc[3][2];
#pragma unroll
        for (int t = 0; t < 3; t++) { acc[t][0] = bias0; acc[t][1] = bias1; }
        const float2* wv = (const float2*)s_w;      // [(ci*49+k)*2 + pr]
#pragma unroll
        for (int ci = 0; ci < 3; ci++) {
#pragma unroll
            for (int kh = 0; kh < 7; kh++) {
                const float2* rp = (const float2*)(s_in + ci*2090 + (oh*2 + kh)*110 + ow0*2);
                float2 q0 = rp[0], q1 = rp[1], q2 = rp[2], q3 = rp[3], q4 = rp[4], q5 = rp[5];
                float v[11] = {q0.x,q0.y,q1.x,q1.y,q2.x,q2.y,q3.x,q3.y,q4.x,q4.y,q5.x};
#pragma unroll
                for (int kw = 0; kw < 7; kw++) {
                    float2 wa = wv[(ci*49 + kh*7 + kw)*2 + 0];
                    float2 wb = wv[(ci*49 + kh*7 + kw)*2 + 1];
#pragma unroll
                    for (int t = 0; t < 3; t++) {
                        float2 iv = bcast2(v[kw + 2*t]);
                        ffma2(acc[t][0], iv, wa);
                        ffma2(acc[t][1], iv, wb);
                    }
                }
            }
        }
#pragma unroll
        for (int t = 0; t < 3; t++) {
            s_c[0*357 + oh*51 + ow0 + t] = fmaxf(acc[t][0].x, 0.f);
            s_c[1*357 + oh*51 + ow0 + t] = fmaxf(acc[t][0].y, 0.f);
            s_c[2*357 + oh*51 + ow0 + t] = fmaxf(acc[t][1].x, 0.f);
            s_c[3*357 + oh*51 + ow0 + t] = fmaxf(acc[t][1].y, 0.f);
        }
    }
    __syncthreads();
    // pool 3x3 s2: 4co x 3 pool rows x 25 cols -> padded interior of g_p1
    for (int q = threadIdx.x; q < 300; q += 128) {
        int u = q / 75, qq = q % 75, pr2 = qq / 25, pc = qq % 25;
        const float* c = s_c + u*357 + (pr2*2)*51 + pc*2;
        float m = fmaxf(fmaxf(c[0], c[1]), c[2]);
        m = fmaxf(m, fmaxf(fmaxf(c[51], c[52]), c[53]));
        m = fmaxf(m, fmaxf(fmaxf(c[102], c[103]), c[104]));
        g_p1[((b*32 + co0 + u) * 16 + (2 + 3*g + pr2)) * 30 + (2 + pc)] = m;
    }
}

// ---------------------------------------------------------------------------
// 3. conv2 5x5 (32->64) + relu + pool 2x2 -> g_p2 interior.
//    Grid = (b10 x cog32 of 2co) = 320 blocks x 480 threads.
//    Thread: cii 0..3 (compile-time) x oh x 5ow; 5 float2 chains.
__global__ void __launch_bounds__(480, 1) conv2_pool2(const float* __restrict__ w2,
                                                      const float* __restrict__ b2) {
    extern __shared__ float sm[];
    float* s_in   = sm;            // 32*16*30 = 15360
    float* s_w    = sm + 15360;    // 2*800 = 1600 (co-interleaved)
    float* s_part = sm + 16960;    // 8*600 = 4800
    float* s_c    = sm + 21760;    // 2*300 = 600
    int b = blockIdx.x >> 5, cog = blockIdx.x & 31;
    int co0 = cog * 2;
    {
        const float4* src = (const float4*)(g_p1 + b * 15360);
        float4* dst = (float4*)s_in;
        for (int i = threadIdx.x; i < 3840; i += 480) dst[i] = src[i];
        for (int i = threadIdx.x; i < 1600; i += 480)
            s_w[i] = w2[(co0 + (i & 1)) * 800 + (i >> 1)];
    }
    __syncthreads();
    {
        int ciq = threadIdx.x / 60, rem = threadIdx.x % 60;
        int oh = rem / 5, ow0 = (rem % 5) * 5;
        float2 acc[5] = {};
        const float2* wv = (const float2*)s_w;
        int ci0 = ciq * 4;
#pragma unroll
        for (int cii = 0; cii < 4; cii++) {
            int ci = ci0 + cii;
#pragma unroll
            for (int kh = 0; kh < 5; kh++) {
                const float* rp = s_in + ci*480 + (oh + kh)*30 + ow0;
                float v[9];
#pragma unroll
                for (int m = 0; m < 9; m++) v[m] = rp[m];
                float2 w[5];
#pragma unroll
                for (int kw = 0; kw < 5; kw++) w[kw] = wv[ci*25 + kh*5 + kw];
#pragma unroll
                for (int kw = 0; kw < 5; kw++) {
#pragma unroll
                    for (int t = 0; t < 5; t++)
                        ffma2(acc[t], bcast2(v[kw+t]), w[kw]);
                }
            }
        }
        float* pp = s_part + ciq*600 + oh*50 + ow0*2;
#pragma unroll
        for (int t = 0; t < 5; t++) { pp[t*2] = acc[t].x; pp[t*2+1] = acc[t].y; }
    }
    __syncthreads();
    for (int o = threadIdx.x; o < 600; o += 480) {
        int coin = o & 1, pos = o >> 1;
        float v = b2[co0 + coin];
#pragma unroll
        for (int q = 0; q < 8; q++) v += s_part[q*600 + o];
        s_c[coin*300 + pos] = fmaxf(v, 0.f);
    }
    __syncthreads();
    if (threadIdx.x < 144) {
        int u = threadIdx.x / 72, rc = threadIdx.x % 72;
        int rr = rc / 12, cl = rc % 12;
        const float* c = s_c + u*300 + (rr*2)*25 + cl*2;
        float v = fmaxf(fmaxf(c[0], c[1]), fmaxf(c[25], c[26]));
        g_p2[((b*64 + co0 + u) * 8 + (rr + 1)) * 14 + (cl + 1)] = v;
    }
}

// ---------------------------------------------------------------------------
// 4. conv3 3x3 (64->128) + relu + pool 2x2 + global-avg. WEIGHTS IN REGISTERS.
//    Grid = (b10 x cog32 of 4co) = 320 blocks x 576 threads.
//    Thread: ciq16(4ci) x pair2 x oh6 x owq3; 36 float2 weights in regs.
__global__ void __launch_bounds__(576, 1) conv3_gap(const float* __restrict__ w3,
                                                    const float* __restrict__ b3) {
    extern __shared__ float sm[];
    float* s_in   = sm;            // 64*8*14 = 7168
    float* s_w    = sm + 7168;     // 4*576 = 2304 (pair/coin interleaved)
    float* s_part = sm + 9472;     // 16*288 = 4608
    float* s_c    = sm + 14080;    // 4*72 = 288
    float* s_p    = sm + 14368;    // 72
    int b = blockIdx.x >> 5, cog = blockIdx.x & 31;
    int cb = cog * 4;
    {
        const float4* src = (const float4*)(g_p2 + b * 7168);
        float4* dst = (float4*)s_in;
        for (int i = threadIdx.x; i < 1792; i += 576) dst[i] = src[i];
        for (int i = threadIdx.x; i < 2304; i += 576) {
            int coin = i & 1, pr = (i >> 1) & 1, j = i >> 2;
            s_w[i] = w3[(cb + pr*2 + coin) * 576 + j];
        }
    }
    __syncthreads();
    {
        int ciq = threadIdx.x / 36, sub = threadIdx.x % 36;
        int pair = sub / 18, oh = (sub % 18) / 3, owq = sub % 3;
        int ow0 = owq * 4;
        int ci0 = ciq * 4;
        const float2* wv = (const float2*)s_w;      // [(ci*9+k)*2 + pair]
        float2 wreg[36];
#pragma unroll
        for (int cii = 0; cii < 4; cii++)
#pragma unroll
            for (int k = 0; k < 9; k++)
                wreg[cii*9 + k] = wv[((ci0 + cii)*9 + k)*2 + pair];
        float2 acc[4] = {};
#pragma unroll
        for (int cii = 0; cii < 4; cii++) {
            int ci = ci0 + cii;
#pragma unroll
            for (int kh = 0; kh < 3; kh++) {
                const float2* rp = (const float2*)(s_in + ci*112 + (oh + kh)*14 + ow0);
                float2 p0 = rp[0], p1 = rp[1], p2 = rp[2];
                float v[6] = {p0.x, p0.y, p1.x, p1.y, p2.x, p2.y};
#pragma unroll
                for (int kw = 0; kw < 3; kw++) {
                    float2 w = wreg[cii*9 + kh*3 + kw];
#pragma unroll
                    for (int t = 0; t < 4; t++)
                        ffma2(acc[t], bcast2(v[kw+t]), w);
                }
            }
        }
        float* pp = s_part + ciq*288 + sub*8;
#pragma unroll
        for (int t = 0; t < 4; t++) { pp[t*2] = acc[t].x; pp[t*2+1] = acc[t].y; }
    }
    __syncthreads();
    if (threadIdx.x < 288) {
        int o = threadIdx.x;
        int co_l = o / 72, pos = o % 72;
        int oh2 = pos / 12, ow = pos % 12;
        int owq = ow >> 2, ti = ow & 3;
        int pair = co_l >> 1, coin = co_l & 1;
        int idx = (pair*18 + oh2*3 + owq)*8 + ti*2 + coin;
        float v = b3[cb + co_l];
#pragma unroll
        for (int q = 0; q < 16; q++) v += s_part[q*288 + idx];
        s_c[co_l*72 + pos] = fmaxf(v, 0.f);
    }
    __syncthreads();
    if (threadIdx.x < 72) {
        int co_l = threadIdx.x / 18, cell = threadIdx.x % 18;
        int ph = cell / 6, pw = cell % 6;
        const float* c = s_c + co_l*72 + (ph*2)*12 + pw*2;
        s_p[threadIdx.x] = fmaxf(fmaxf(c[0], c[1]), fmaxf(c[12], c[13]));
    }
    __syncthreads();
    if (threadIdx.x < 4) {
        float s = 0.f;
#pragma unroll
        for (int i = 0; i < 18; i++) s += s_p[threadIdx.x*18 + i];
        g_gap[b*128 + cb + threadIdx.x] = s * (1.0f/18.0f);
    }
}

// ---------------------------------------------------------------------------
// 5. fc1(128->128)+relu, fc2(128->5). One block per batch row.
__global__ void fc_fused(const float* __restrict__ wl1, const float* __restrict__ bl1,
                         const float* __restrict__ wl2, const float* __restrict__ bl2,
                         float* __restrict__ out) {
    __shared__ float s_g[128];
    __shared__ float s_h[128];
    int b = blockIdx.x;
    int t = threadIdx.x;
    s_g[t] = g_gap[b*128 + t];
    __syncthreads();
    float s = bl1[t];
    const float* wr = wl1 + t*128;
#pragma unroll 8
    for (int i = 0; i < 128; i++) s += s_g[i] * wr[i];
    s_h[t] = fmaxf(s, 0.f);
    __syncthreads();
    if (t < 5) {
        float o = bl2[t];
        const float* wr2 = wl2 + t*128;
#pragma unroll 8
        for (int i = 0; i < 128; i++) o += s_h[i] * wr2[i];
        out[b*5 + t] = o;
    }
}

extern "C" void kernel_launch(void* const* d_in, const int* in_sizes, int n_in,
                              void* d_out, int out_size) {
    const int*   x   = (const int*)  d_in[0];
    const float* w1  = (const float*)d_in[1];
    const float* b1  = (const float*)d_in[2];
    const float* w2  = (const float*)d_in[3];
    const float* b2  = (const float*)d_in[4];
    const float* w3  = (const float*)d_in[5];
    const float* b3  = (const float*)d_in[6];
    const float* wl1 = (const float*)d_in[7];
    const float* bl1 = (const float*)d_in[8];
    const float* wl2 = (const float*)d_in[9];
    const float* bl2 = (const float*)d_in[10];
    float* out = (float*)d_out;

    const int smem1 = (6270 + 588 + 1428) * 4;              // 33144 B
    const int smem2 = (15360 + 1600 + 4800 + 600) * 4;      // 89440 B
    const int smem3 = (7168 + 2304 + 4608 + 288 + 72) * 4;  // 57760 B
    cudaFuncSetAttribute(conv1_pool1, cudaFuncAttributeMaxDynamicSharedMemorySize, smem1);
    cudaFuncSetAttribute(conv2_pool2, cudaFuncAttributeMaxDynamicSharedMemorySize, smem2);
    cudaFuncSetAttribute(conv3_gap,   cudaFuncAttributeMaxDynamicSharedMemorySize, smem3);

    build_grid <<<BB*CC, 1024>>>(x);
    conv1_pool1<<<BB*32, 128, smem1>>>(w1, b1);
    conv2_pool2<<<BB*32, 480, smem2>>>(w2, b2);
    conv3_gap  <<<BB*32, 576, smem3>>>(w3, b3);
    fc_fused   <<<BB, 128>>>(wl1, bl1, wl2, bl2, out);
}